// round 10
// baseline (speedup 1.0000x reference)
#include <cuda_runtime.h>
#include <math.h>

#define R 5
#define E 50000
#define NU 20000
#define NI 20000
#define NF 4
#define DN 16
#define DR 64
#define DRP 68   // padded row stride (floats) for conflict-free smem
#define DO 64
#define TAUINV 2.0f   // 1/TAU, TAU = 0.5
#define EPW 8         // edges per warp in stream role
#define WARPS 8       // warps per block
#define EPB (EPW * WARPS)
#define NBS_PER_R ((E + EPB - 1) / EPB)   // 782
#define NB_STREAM (NBS_PER_R * R)         // 3910
#define NB_SIM (((size_t)R * E * 4 + 255) / 256)  // 3907

// ---------------- scratch (__device__ globals; no allocation allowed) ----------------
__device__ float d_ganchor[R * E];   // g * exp_anchor
__device__ float d_simpart[R * E];   // (1-g) * exp_sim
__device__ float d_rfw[(size_t)R * E * DN];
__device__ float d_rfr[(size_t)R * E * DN];
__device__ float d_hu[(size_t)R * NU * DN];
__device__ float d_hi[(size_t)R * NI * DN];
__device__ float d_norm_u[NU];
__device__ float d_norm_i[NI];
__device__ float d_umsg[NU * DN];
__device__ float d_imsg[NI * DN];

// ---------------- kernel 0a/0b: zero accumulators ----------------
__global__ void zero_norm_kernel() {
    int g = blockIdx.x * blockDim.x + threadIdx.x;
    if (g < NU) d_norm_u[g] = 0.f;
    if (g < NI) d_norm_i[g] = 0.f;
}
__global__ void zero_msg_kernel() {
    int g = blockIdx.x * blockDim.x + threadIdx.x;
    if (g < NU * DN) d_umsg[g] = 0.f;
    if (g < NI * DN) d_imsg[g] = 0.f;
}

// ---------------- kernel 1: hu = uh @ Wfwd^T, hi = ih @ Wrev^T ----------------
__global__ void node_proj_kernel(const float* __restrict__ user_h,
                                 const float* __restrict__ item_h,
                                 const float* __restrict__ wfwd,
                                 const float* __restrict__ wrev,
                                 const int* __restrict__ kp) {
    __shared__ float sW[DN * DN];
    int r = blockIdx.y;
    int which = blockIdx.z;
    const float* W = which ? (wrev + r * DN * DN) : (wfwd + r * DN * DN);
    if (threadIdx.x < DN * DN) sW[threadIdx.x] = W[threadIdx.x];
    __syncthreads();
    int g = blockIdx.x * blockDim.x + threadIdx.x;
    int n = g >> 4;
    int o = g & 15;
    if (n >= NU) return;   // NU == NI
    int kk = *kp;
    const float* H = which ? (item_h + ((size_t)(kk * R + r) * NI + n) * DN)
                           : (user_h + ((size_t)(kk * R + r) * NU + n) * DN);
    float acc = 0.f;
#pragma unroll
    for (int d = 0; d < DN; d++) acc += H[d] * sW[o * DN + d];
    if (which) d_hi[((size_t)r * NI + n) * DN + o] = acc;
    else       d_hu[((size_t)r * NU + n) * DN + o] = acc;
}

// ---------------- kernel 2: FUSED edge pass (stream role + sim role) ----------------
// role A (blocks [0, NB_STREAM)): streams rfeat -> ganchor + norm contrib + rfw/rfr
// role B (blocks [NB_STREAM, NB_STREAM+NB_SIM)): gathers -> simpart + norm contrib
__global__ void fused_edge_kernel(const float* __restrict__ user_h,
                                  const float* __restrict__ item_h,
                                  const float* __restrict__ uhs,
                                  const float* __restrict__ ihs,
                                  const float* __restrict__ rfeat,
                                  const float* __restrict__ proto,
                                  const float* __restrict__ eta,
                                  const float* __restrict__ rwf,
                                  const float* __restrict__ rwr,
                                  const int* __restrict__ esrc,
                                  const int* __restrict__ edst,
                                  const int* __restrict__ kp) {
    __shared__ __align__(16) float s_proto[NF * DR];
    __shared__ __align__(16) float s_wf[DN * DRP];   // padded: row stride 68
    __shared__ __align__(16) float s_wr[DN * DRP];
    __shared__ __align__(16) float s_stage[WARPS][EPW][DR];   // 16 KB

    const unsigned FULL = 0xffffffffu;
    int tid = threadIdx.x;
    int kk = *kp;

    if (blockIdx.x >= NB_STREAM) {
        // ================= role B: 4-lanes-per-edge sim =================
        long long g = (long long)(blockIdx.x - NB_STREAM) * blockDim.x + tid;
        long long eidx = g >> 2;
        int l = (int)(g & 3);          // this lane's factor index f = l
        if (eidx >= (long long)R * E) return;
        size_t idx = (size_t)eidx;
        int r = (int)(eidx / E);
        int src = esrc[idx], dst = edst[idx];

        // cosine sim: 4 lanes each load one float4 of u and v
        float4 a = *(const float4*)(user_h + ((size_t)(kk * R + r) * NU + src) * DN + l * 4);
        float4 b = *(const float4*)(item_h + ((size_t)(kk * R + r) * NI + dst) * DN + l * 4);
        float su  = a.x * a.x + a.y * a.y + a.z * a.z + a.w * a.w;
        float sv  = b.x * b.x + b.y * b.y + b.z * b.z + b.w * b.w;
        float suv = a.x * b.x + a.y * b.y + a.z * b.z + a.w * b.w;
#pragma unroll
        for (int off = 1; off <= 2; off <<= 1) {
            su  += __shfl_xor_sync(FULL, su,  off);
            sv  += __shfl_xor_sync(FULL, sv,  off);
            suv += __shfl_xor_sync(FULL, suv, off);
        }
        float sim_k = suv / fmaxf(sqrtf(su), 1e-12f) / fmaxf(sqrtf(sv), 1e-12f) * TAUINV;

        // softmax denominator: lane l handles factor f=l
        const float4* ra4 = (const float4*)(uhs + ((size_t)r * NU + src) * (NF * DN) + l * DN);
        const float4* ca4 = (const float4*)(ihs + ((size_t)r * NI + dst) * (NF * DN) + l * DN);
        float s = 0.f;
#pragma unroll
        for (int i = 0; i < 4; i++) {
            float4 x = ra4[i], y = ca4[i];
            s += x.x * y.x + x.y * y.y + x.z * y.z + x.w * y.w;
        }
        float sumexp = __expf(s * TAUINV);
#pragma unroll
        for (int off = 1; off <= 2; off <<= 1)
            sumexp += __shfl_xor_sync(FULL, sumexp, off);

        float exp_sim = __expf(sim_k) / sumexp;
        float gg = 1.f / (1.f + __expf(-eta[idx]));
        float sp = (1.f - gg) * exp_sim;
        if (l == 0) {
            d_simpart[idx] = sp;
            atomicAdd(&d_norm_u[src], sp);
            atomicAdd(&d_norm_i[dst], sp);
        }
        return;
    }

    // ================= role A: streaming anchor + projections =================
    int r = blockIdx.x / NBS_PER_R;
    int bx = blockIdx.x % NBS_PER_R;

    for (int i = tid; i < NF * DR; i += 256) s_proto[i] = proto[i];
    for (int i = tid; i < DN * DR; i += 256) {
        int row = i >> 6, col = i & 63;
        s_wf[row * DRP + col] = rwf[r * DN * DR + i];
        s_wr[row * DRP + col] = rwr[r * DN * DR + i];
    }
    __syncthreads();

    int warp = tid >> 5, lane = tid & 31;
    int d0 = (lane * 4) & 63;
    int f1 = lane >> 4;
    int f2 = 2 + f1;
    int o = lane & 15;
    float4 w1 = *(const float4*)(s_proto + f1 * DR + d0);
    float4 w2 = *(const float4*)(s_proto + f2 * DR + d0);

    int ebase = bx * EPB;

    // ---- phase 1: anchor softmax + stage rf_k + norm contribution ----
#pragma unroll 2
    for (int it = 0; it < EPW; it++) {
        int e = ebase + it * WARPS + warp;   // consecutive warps -> consecutive slabs
        if (e >= E) break;
        size_t idx = (size_t)r * E + e;

        const float4* rf = (const float4*)(rfeat + idx * (size_t)(NF * DR));
        float4 v1 = rf[lane];        // f = lane/16        (f0/f1)
        float4 v2 = rf[lane + 32];   // f = 2 + lane/16    (f2/f3)
        float p1 = v1.x * w1.x + v1.y * w1.y + v1.z * w1.z + v1.w * w1.w;
        float p2 = v2.x * w2.x + v2.y * w2.y + v2.z * w2.z + v2.w * w2.w;
        if (f1 == kk) *(float4*)&s_stage[warp][it][d0] = v1;
        if (f2 == kk) *(float4*)&s_stage[warp][it][d0] = v2;
#pragma unroll
        for (int off = 8; off >= 1; off >>= 1) {
            p1 += __shfl_xor_sync(FULL, p1, off);
            p2 += __shfl_xor_sync(FULL, p2, off);
        }
        float a0 = __shfl_sync(FULL, p1, 0);
        float a1 = __shfl_sync(FULL, p1, 16);
        float a2 = __shfl_sync(FULL, p2, 0);
        float a3 = __shfl_sync(FULL, p2, 16);
        float ea0 = __expf(a0 * TAUINV), ea1 = __expf(a1 * TAUINV);
        float ea2 = __expf(a2 * TAUINV), ea3 = __expf(a3 * TAUINV);
        float eak = (kk == 0) ? ea0 : (kk == 1) ? ea1 : (kk == 2) ? ea2 : ea3;
        if (lane == 0) {
            float exp_anchor = eak / (ea0 + ea1 + ea2 + ea3);
            float gg = 1.f / (1.f + __expf(-eta[idx]));
            float ga = gg * exp_anchor;
            d_ganchor[idx] = ga;
            atomicAdd(&d_norm_u[esrc[idx]], ga);
            atomicAdd(&d_norm_i[edst[idx]], ga);
        }
    }

    // ---- phase 2: batched review projections ----
    __syncwarp();
    float acc[EPW];
#pragma unroll
    for (int j = 0; j < EPW; j++) acc[j] = 0.f;
    const float* Wrow = (lane < 16) ? (s_wf + o * DRP) : (s_wr + o * DRP);
#pragma unroll
    for (int c = 0; c < 4; c++) {           // 16 d-values per chunk
        float4 wc0 = *(const float4*)&Wrow[c * 16];
        float4 wc1 = *(const float4*)&Wrow[c * 16 + 4];
        float4 wc2 = *(const float4*)&Wrow[c * 16 + 8];
        float4 wc3 = *(const float4*)&Wrow[c * 16 + 12];
#pragma unroll
        for (int j = 0; j < EPW; j++) {
            float4 s0 = *(const float4*)&s_stage[warp][j][c * 16];
            float4 s1 = *(const float4*)&s_stage[warp][j][c * 16 + 4];
            float4 s2 = *(const float4*)&s_stage[warp][j][c * 16 + 8];
            float4 s3 = *(const float4*)&s_stage[warp][j][c * 16 + 12];
            acc[j] += s0.x * wc0.x + s0.y * wc0.y + s0.z * wc0.z + s0.w * wc0.w
                    + s1.x * wc1.x + s1.y * wc1.y + s1.z * wc1.z + s1.w * wc1.w
                    + s2.x * wc2.x + s2.y * wc2.y + s2.z * wc2.z + s2.w * wc2.w
                    + s3.x * wc3.x + s3.y * wc3.y + s3.z * wc3.z + s3.w * wc3.w;
        }
    }
#pragma unroll
    for (int j = 0; j < EPW; j++) {
        int e = ebase + j * WARPS + warp;
        if (e < E) {
            size_t idx = (size_t)r * E + e;
            if (lane < 16) d_rfw[idx * DN + o] = acc[j];
            else           d_rfr[idx * DN + o] = acc[j];
        }
    }
}

// ---------------- kernel 3: per-edge pass 2 — weight + scatter (v4 reductions) --------
__global__ void edge2_kernel(const int* __restrict__ esrc,
                             const int* __restrict__ edst,
                             float* __restrict__ out_int) {
    size_t g = (size_t)blockIdx.x * blockDim.x + threadIdx.x;
    size_t idx = g >> 2;
    int q4 = (int)(g & 3) * 4;       // quarter offset 0,4,8,12
    if (idx >= (size_t)R * E) return;
    int src = esrc[idx], dst = edst[idx];
    int r = (int)(idx / E);
    float b = d_ganchor[idx] + d_simpart[idx];
    float w = b * rsqrtf(d_norm_u[src] * d_norm_i[dst]);
    if (q4 == 0) out_int[idx] = w;

    float4 hu4 = *(const float4*)&d_hu[((size_t)r * NU + src) * DN + q4];
    float4 rw4 = *(const float4*)&d_rfw[idx * DN + q4];
    float4 mf = make_float4((hu4.x + rw4.x) * w, (hu4.y + rw4.y) * w,
                            (hu4.z + rw4.z) * w, (hu4.w + rw4.w) * w);
    asm volatile("red.global.add.v4.f32 [%0], {%1, %2, %3, %4};"
                 :: "l"(&d_imsg[(size_t)dst * DN + q4]),
                    "f"(mf.x), "f"(mf.y), "f"(mf.z), "f"(mf.w) : "memory");

    float4 hi4 = *(const float4*)&d_hi[((size_t)r * NI + dst) * DN + q4];
    float4 rr4 = *(const float4*)&d_rfr[idx * DN + q4];
    float4 mr = make_float4((hi4.x + rr4.x) * w, (hi4.y + rr4.y) * w,
                            (hi4.z + rr4.z) * w, (hi4.w + rr4.w) * w);
    asm volatile("red.global.add.v4.f32 [%0], {%1, %2, %3, %4};"
                 :: "l"(&d_umsg[(size_t)src * DN + q4]),
                    "f"(mr.x), "f"(mr.y), "f"(mr.z), "f"(mr.w) : "memory");
}

// ---------------- kernel 4: leaky_relu + FC (16 -> 64), both sides ----------------
__global__ void fc_kernel(const float* __restrict__ uW,
                          const float* __restrict__ ub,
                          const float* __restrict__ iW,
                          const float* __restrict__ ib,
                          float* __restrict__ out_u,
                          float* __restrict__ out_i) {
    __shared__ float sW[DO * DN];
    __shared__ float sb[DO];
    int which = blockIdx.y;
    const float* W = which ? iW : uW;
    const float* bias = which ? ib : ub;
    for (int i = threadIdx.x; i < DO * DN; i += 256) sW[i] = W[i];
    if (threadIdx.x < DO) sb[threadIdx.x] = bias[threadIdx.x];
    __syncthreads();
    int g = blockIdx.x * blockDim.x + threadIdx.x;
    int n = g >> 6;
    int o = g & 63;
    if (n >= NU) return;   // NU == NI
    const float* msg = which ? d_imsg : d_umsg;
    float acc = sb[o];
#pragma unroll
    for (int d = 0; d < DN; d++) {
        float x = msg[n * DN + d];
        x = (x >= 0.f) ? x : 0.1f * x;
        acc += x * sW[o * DN + d];
    }
    float* out = which ? out_i : out_u;
    out[(size_t)n * DO + o] = acc;
}

// ---------------- launch ----------------
extern "C" void kernel_launch(void* const* d_in, const int* in_sizes, int n_in,
                              void* d_out, int out_size) {
    const float* user_h    = (const float*)d_in[0];
    const float* item_h    = (const float*)d_in[1];
    const float* user_hsum = (const float*)d_in[2];
    const float* item_hsum = (const float*)d_in[3];
    const float* rfeat     = (const float*)d_in[4];
    const float* proto     = (const float*)d_in[5];
    const float* eta       = (const float*)d_in[6];
    const float* nwf       = (const float*)d_in[7];
    const float* rwf       = (const float*)d_in[8];
    const float* nwr       = (const float*)d_in[9];
    const float* rwr       = (const float*)d_in[10];
    const float* ufc_w     = (const float*)d_in[11];
    const float* ufc_b     = (const float*)d_in[12];
    const float* ifc_w     = (const float*)d_in[13];
    const float* ifc_b     = (const float*)d_in[14];
    const int*   esrc      = (const int*)d_in[15];
    const int*   edst      = (const int*)d_in[16];
    const int*   kp        = (const int*)d_in[17];
    float* out = (float*)d_out;

    float* out_ufeat = out;
    float* out_ifeat = out + (size_t)NU * DO;
    float* out_int   = out + (size_t)NU * DO + (size_t)NI * DO;

    // launch #1, #2
    zero_norm_kernel<<<(NU + 255) / 256, 256>>>();
    zero_msg_kernel<<<(NU * DN + 255) / 256, 256>>>();

    // launch #3
    dim3 gn((NU * DN + 255) / 256, R, 2);
    node_proj_kernel<<<gn, 256>>>(user_h, item_h, nwf, nwr, kp);

    // launch #4 (profiled): fused stream + sim
    fused_edge_kernel<<<NB_STREAM + (unsigned)NB_SIM, 256>>>(
        user_h, item_h, user_hsum, item_hsum, rfeat, proto, eta,
        rwf, rwr, esrc, edst, kp);

    // launch #5
    edge2_kernel<<<((size_t)R * E * 4 + 255) / 256, 256>>>(esrc, edst, out_int);

    // launch #6
    dim3 gfc((NU * DO + 255) / 256, 2);
    fc_kernel<<<gfc, 256>>>(ufc_w, ufc_b, ifc_w, ifc_b, out_ufeat, out_ifeat);
}

// round 12
// speedup vs baseline: 1.1088x; 1.1088x over previous
#include <cuda_runtime.h>
#include <math.h>

#define R 5
#define E 50000
#define NU 20000
#define NI 20000
#define NF 4
#define DN 16
#define DR 64
#define DRP 68   // padded row stride (floats) for conflict-free smem
#define DO 64
#define TAUINV 2.0f   // 1/TAU, TAU = 0.5
#define EPW 8         // edges per warp in edge1
#define WARPS 8       // warps per block in edge1
#define EPB (EPW * WARPS)

// ---------------- scratch (__device__ globals; no allocation allowed) ----------------
__device__ float d_anchor[R * E];
__device__ float d_blended[R * E];
__device__ float d_rfw[(size_t)R * E * DN];
__device__ float d_rfr[(size_t)R * E * DN];
__device__ float d_hu[(size_t)R * NU * DN];
__device__ float d_hi[(size_t)R * NI * DN];
__device__ float d_norm_u[NU];
__device__ float d_norm_i[NI];
__device__ float d_umsg[NU * DN];
__device__ float d_imsg[NI * DN];

// ---------------- kernel 0a/0b: zero accumulators ----------------
__global__ void zero_norm_kernel() {
    int g = blockIdx.x * blockDim.x + threadIdx.x;
    if (g < NU) d_norm_u[g] = 0.f;
    if (g < NI) d_norm_i[g] = 0.f;
}
__global__ void zero_msg_kernel() {
    int g = blockIdx.x * blockDim.x + threadIdx.x;
    if (g < NU * DN) d_umsg[g] = 0.f;
    if (g < NI * DN) d_imsg[g] = 0.f;
}

// ---------------- kernel 1: hu = uh @ Wfwd^T, hi = ih @ Wrev^T ----------------
__global__ void node_proj_kernel(const float* __restrict__ user_h,
                                 const float* __restrict__ item_h,
                                 const float* __restrict__ wfwd,
                                 const float* __restrict__ wrev,
                                 const int* __restrict__ kp) {
    __shared__ float sW[DN * DN];
    int r = blockIdx.y;
    int which = blockIdx.z;
    const float* W = which ? (wrev + r * DN * DN) : (wfwd + r * DN * DN);
    if (threadIdx.x < DN * DN) sW[threadIdx.x] = W[threadIdx.x];
    __syncthreads();
    int g = blockIdx.x * blockDim.x + threadIdx.x;
    int n = g >> 4;
    int o = g & 15;
    if (n >= NU) return;   // NU == NI
    int kk = *kp;
    const float* H = which ? (item_h + ((size_t)(kk * R + r) * NI + n) * DN)
                           : (user_h + ((size_t)(kk * R + r) * NU + n) * DN);
    float acc = 0.f;
#pragma unroll
    for (int d = 0; d < DN; d++) acc += H[d] * sW[o * DN + d];
    if (which) d_hi[((size_t)r * NI + n) * DN + o] = acc;
    else       d_hu[((size_t)r * NU + n) * DN + o] = acc;
}

// ---------------- kernel 2: streaming pass — anchor softmax + review projections ------
__global__ __launch_bounds__(256, 6)
void edge1_kernel(const float* __restrict__ rfeat,
                  const float* __restrict__ proto,
                  const float* __restrict__ rwf,
                  const float* __restrict__ rwr,
                  const int* __restrict__ kp) {
    __shared__ __align__(16) float s_proto[NF * DR];
    __shared__ __align__(16) float s_wf[DN * DRP];   // padded: row stride 68
    __shared__ __align__(16) float s_wr[DN * DRP];
    __shared__ __align__(16) float s_stage[WARPS][EPW][DR];   // 16 KB

    const unsigned FULL = 0xffffffffu;
    int r = blockIdx.y;
    int tid = threadIdx.x;
    for (int i = tid; i < NF * DR; i += 256) s_proto[i] = proto[i];
    for (int i = tid; i < DN * DR; i += 256) {
        int row = i >> 6, col = i & 63;
        s_wf[row * DRP + col] = rwf[r * DN * DR + i];
        s_wr[row * DRP + col] = rwr[r * DN * DR + i];
    }
    __syncthreads();

    int warp = tid >> 5, lane = tid & 31;
    int kk = *kp;
    int d0 = (lane * 4) & 63;
    int f1 = lane >> 4;
    int f2 = 2 + f1;
    int o = lane & 15;
    float4 w1 = *(const float4*)(s_proto + f1 * DR + d0);
    float4 w2 = *(const float4*)(s_proto + f2 * DR + d0);

    int ebase = blockIdx.x * EPB;

    // ================= phase 1: anchor softmax + stage rf_k =================
#pragma unroll 2
    for (int it = 0; it < EPW; it++) {
        int e = ebase + it * WARPS + warp;   // consecutive warps -> consecutive slabs
        if (e >= E) break;
        size_t idx = (size_t)r * E + e;

        const float4* rf = (const float4*)(rfeat + idx * (size_t)(NF * DR));
        float4 v1 = rf[lane];        // f = lane/16        (f0/f1)
        float4 v2 = rf[lane + 32];   // f = 2 + lane/16    (f2/f3)
        float p1 = v1.x * w1.x + v1.y * w1.y + v1.z * w1.z + v1.w * w1.w;
        float p2 = v2.x * w2.x + v2.y * w2.y + v2.z * w2.z + v2.w * w2.w;
        // stage the k-slice rf_k (64 floats) into smem for the batched projections
        if (f1 == kk) *(float4*)&s_stage[warp][it][d0] = v1;
        if (f2 == kk) *(float4*)&s_stage[warp][it][d0] = v2;
#pragma unroll
        for (int off = 8; off >= 1; off >>= 1) {
            p1 += __shfl_xor_sync(FULL, p1, off);
            p2 += __shfl_xor_sync(FULL, p2, off);
        }
        float a0 = __shfl_sync(FULL, p1, 0);
        float a1 = __shfl_sync(FULL, p1, 16);
        float a2 = __shfl_sync(FULL, p2, 0);
        float a3 = __shfl_sync(FULL, p2, 16);
        float ea0 = __expf(a0 * TAUINV), ea1 = __expf(a1 * TAUINV);
        float ea2 = __expf(a2 * TAUINV), ea3 = __expf(a3 * TAUINV);
        float eak = (kk == 0) ? ea0 : (kk == 1) ? ea1 : (kk == 2) ? ea2 : ea3;
        if (lane == 0) d_anchor[idx] = eak / (ea0 + ea1 + ea2 + ea3);
    }

    // ================= phase 2: batched review projections =================
    // one W chunk + one stage chunk live at a time -> low register pressure
    __syncwarp();
    float acc[EPW];
#pragma unroll
    for (int j = 0; j < EPW; j++) acc[j] = 0.f;
    const float* Wrow = (lane < 16) ? (s_wf + o * DRP) : (s_wr + o * DRP);
#pragma unroll
    for (int c = 0; c < 16; c++) {          // 4 d-values per chunk
        float4 wc = *(const float4*)&Wrow[c * 4];
#pragma unroll
        for (int j = 0; j < EPW; j++) {
            float4 s4 = *(const float4*)&s_stage[warp][j][c * 4];
            acc[j] += s4.x * wc.x + s4.y * wc.y + s4.z * wc.z + s4.w * wc.w;
        }
    }
#pragma unroll
    for (int j = 0; j < EPW; j++) {
        int e = ebase + j * WARPS + warp;
        if (e < E) {
            size_t idx = (size_t)r * E + e;
            if (lane < 16) d_rfw[idx * DN + o] = acc[j];
            else           d_rfr[idx * DN + o] = acc[j];
        }
    }
}

// ---------------- kernel 2b: 4-lanes-per-edge sim + blend + norm atomics ----------------
__global__ void edge_sim_kernel(const float* __restrict__ user_h,
                                const float* __restrict__ item_h,
                                const float* __restrict__ uhs,
                                const float* __restrict__ ihs,
                                const float* __restrict__ eta,
                                const int* __restrict__ esrc,
                                const int* __restrict__ edst,
                                const int* __restrict__ kp) {
    const unsigned FULL = 0xffffffffu;
    long long g = (long long)blockIdx.x * blockDim.x + threadIdx.x;
    long long eidx = g >> 2;
    int l = (int)(g & 3);          // this lane's factor index f = l
    if (eidx >= (long long)R * E) return;
    size_t idx = (size_t)eidx;
    int r = (int)(eidx / E);
    int src = esrc[idx], dst = edst[idx];
    int kk = *kp;

    // ---- cosine sim: 4 lanes each load one float4 of u and v ----
    float4 a = *(const float4*)(user_h + ((size_t)(kk * R + r) * NU + src) * DN + l * 4);
    float4 b = *(const float4*)(item_h + ((size_t)(kk * R + r) * NI + dst) * DN + l * 4);
    float su  = a.x * a.x + a.y * a.y + a.z * a.z + a.w * a.w;
    float sv  = b.x * b.x + b.y * b.y + b.z * b.z + b.w * b.w;
    float suv = a.x * b.x + a.y * b.y + a.z * b.z + a.w * b.w;
#pragma unroll
    for (int off = 1; off <= 2; off <<= 1) {
        su  += __shfl_xor_sync(FULL, su,  off);
        sv  += __shfl_xor_sync(FULL, sv,  off);
        suv += __shfl_xor_sync(FULL, suv, off);
    }
    float sim_k = suv / fmaxf(sqrtf(su), 1e-12f) / fmaxf(sqrtf(sv), 1e-12f) * TAUINV;

    // ---- softmax denominator: lane l handles factor f=l (16 floats of each row) ----
    const float4* ra4 = (const float4*)(uhs + ((size_t)r * NU + src) * (NF * DN) + l * DN);
    const float4* ca4 = (const float4*)(ihs + ((size_t)r * NI + dst) * (NF * DN) + l * DN);
    float s = 0.f;
#pragma unroll
    for (int i = 0; i < 4; i++) {
        float4 x = ra4[i], y = ca4[i];
        s += x.x * y.x + x.y * y.y + x.z * y.z + x.w * y.w;
    }
    float sumexp = __expf(s * TAUINV);
#pragma unroll
    for (int off = 1; off <= 2; off <<= 1)
        sumexp += __shfl_xor_sync(FULL, sumexp, off);

    float exp_sim = __expf(sim_k) / sumexp;
    float gg = 1.f / (1.f + __expf(-eta[idx]));
    float blended = gg * d_anchor[idx] + (1.f - gg) * exp_sim;
    if (l == 0) {
        d_blended[idx] = blended;
        atomicAdd(&d_norm_u[src], blended);
        atomicAdd(&d_norm_i[dst], blended);
    }
}

// ---------------- kernel 3: per-edge pass 2 — weight + scatter (v4 reductions) --------
__global__ void edge2_kernel(const int* __restrict__ esrc,
                             const int* __restrict__ edst,
                             float* __restrict__ out_int) {
    size_t g = (size_t)blockIdx.x * blockDim.x + threadIdx.x;
    size_t idx = g >> 2;
    int q4 = (int)(g & 3) * 4;       // quarter offset 0,4,8,12
    if (idx >= (size_t)R * E) return;
    int src = esrc[idx], dst = edst[idx];
    int r = (int)(idx / E);
    float b = d_blended[idx];
    float w = b * rsqrtf(d_norm_u[src] * d_norm_i[dst]);
    if (q4 == 0) out_int[idx] = w;

    float4 hu4 = *(const float4*)&d_hu[((size_t)r * NU + src) * DN + q4];
    float4 rw4 = *(const float4*)&d_rfw[idx * DN + q4];
    float4 mf = make_float4((hu4.x + rw4.x) * w, (hu4.y + rw4.y) * w,
                            (hu4.z + rw4.z) * w, (hu4.w + rw4.w) * w);
    asm volatile("red.global.add.v4.f32 [%0], {%1, %2, %3, %4};"
                 :: "l"(&d_imsg[(size_t)dst * DN + q4]),
                    "f"(mf.x), "f"(mf.y), "f"(mf.z), "f"(mf.w) : "memory");

    float4 hi4 = *(const float4*)&d_hi[((size_t)r * NI + dst) * DN + q4];
    float4 rr4 = *(const float4*)&d_rfr[idx * DN + q4];
    float4 mr = make_float4((hi4.x + rr4.x) * w, (hi4.y + rr4.y) * w,
                            (hi4.z + rr4.z) * w, (hi4.w + rr4.w) * w);
    asm volatile("red.global.add.v4.f32 [%0], {%1, %2, %3, %4};"
                 :: "l"(&d_umsg[(size_t)src * DN + q4]),
                    "f"(mr.x), "f"(mr.y), "f"(mr.z), "f"(mr.w) : "memory");
}

// ---------------- kernel 4: leaky_relu + FC (16 -> 64), both sides ----------------
__global__ void fc_kernel(const float* __restrict__ uW,
                          const float* __restrict__ ub,
                          const float* __restrict__ iW,
                          const float* __restrict__ ib,
                          float* __restrict__ out_u,
                          float* __restrict__ out_i) {
    __shared__ float sW[DO * DN];
    __shared__ float sb[DO];
    int which = blockIdx.y;
    const float* W = which ? iW : uW;
    const float* bias = which ? ib : ub;
    for (int i = threadIdx.x; i < DO * DN; i += 256) sW[i] = W[i];
    if (threadIdx.x < DO) sb[threadIdx.x] = bias[threadIdx.x];
    __syncthreads();
    int g = blockIdx.x * blockDim.x + threadIdx.x;
    int n = g >> 6;
    int o = g & 63;
    if (n >= NU) return;   // NU == NI
    const float* msg = which ? d_imsg : d_umsg;
    float acc = sb[o];
#pragma unroll
    for (int d = 0; d < DN; d++) {
        float x = msg[n * DN + d];
        x = (x >= 0.f) ? x : 0.1f * x;
        acc += x * sW[o * DN + d];
    }
    float* out = which ? out_i : out_u;
    out[(size_t)n * DO + o] = acc;
}

// ---------------- launch ----------------
extern "C" void kernel_launch(void* const* d_in, const int* in_sizes, int n_in,
                              void* d_out, int out_size) {
    const float* user_h    = (const float*)d_in[0];
    const float* item_h    = (const float*)d_in[1];
    const float* user_hsum = (const float*)d_in[2];
    const float* item_hsum = (const float*)d_in[3];
    const float* rfeat     = (const float*)d_in[4];
    const float* proto     = (const float*)d_in[5];
    const float* eta       = (const float*)d_in[6];
    const float* nwf       = (const float*)d_in[7];
    const float* rwf       = (const float*)d_in[8];
    const float* nwr       = (const float*)d_in[9];
    const float* rwr       = (const float*)d_in[10];
    const float* ufc_w     = (const float*)d_in[11];
    const float* ufc_b     = (const float*)d_in[12];
    const float* ifc_w     = (const float*)d_in[13];
    const float* ifc_b     = (const float*)d_in[14];
    const int*   esrc      = (const int*)d_in[15];
    const int*   edst      = (const int*)d_in[16];
    const int*   kp        = (const int*)d_in[17];
    float* out = (float*)d_out;

    float* out_ufeat = out;
    float* out_ifeat = out + (size_t)NU * DO;
    float* out_int   = out + (size_t)NU * DO + (size_t)NI * DO;

    // launch #1, #2 (edge1 stays in ncu's captured slot #4)
    zero_norm_kernel<<<(NU + 255) / 256, 256>>>();
    zero_msg_kernel<<<(NU * DN + 255) / 256, 256>>>();

    // launch #3
    dim3 gn((NU * DN + 255) / 256, R, 2);
    node_proj_kernel<<<gn, 256>>>(user_h, item_h, nwf, nwr, kp);

    // launch #4 (profiled): streaming anchor + projections
    dim3 ge((E + EPB - 1) / EPB, R);
    edge1_kernel<<<ge, 256>>>(rfeat, proto, rwf, rwr, kp);

    // launch #5: gather-based sim + blend + norms
    edge_sim_kernel<<<((size_t)R * E * 4 + 255) / 256, 256>>>(user_h, item_h, user_hsum,
                                                              item_hsum, eta, esrc, edst, kp);

    // launch #6
    edge2_kernel<<<((size_t)R * E * 4 + 255) / 256, 256>>>(esrc, edst, out_int);

    // launch #7
    dim3 gfc((NU * DO + 255) / 256, 2);
    fc_kernel<<<gfc, 256>>>(ufc_w, ufc_b, ifc_w, ifc_b, out_ufeat, out_ifeat);
}